// round 2
// baseline (speedup 1.0000x reference)
#include <cuda_runtime.h>

#define B_  4
#define N_  2048
#define H_  16
#define DM_ 1024
#define DK_ 64

// Scratch (device globals — no allocation allowed)
__device__ float g_q[B_*H_*N_*DK_];    // 32 MB, [b,h,n,dk]
__device__ float g_k[B_*H_*N_*DK_];
__device__ float g_v[B_*H_*N_*DK_];
__device__ float g_att[B_*N_*DM_];     // 32 MB, [b,n,h*dv]

// ---------------------------------------------------------------------------
// 128x64 output tile SGEMM, K=1024, BK=16, 128 threads, 8x8 microtile.
// ---------------------------------------------------------------------------
__device__ __forceinline__ void gemm_128x64(
    const float* __restrict__ A, int lda,
    const float* __restrict__ Bm, int ldb,
    const float* __restrict__ bias,
    float* __restrict__ C, int ldc)
{
    __shared__ float sA[16][132];   // [kk][row], pad 132 (≡4 mod 32, 16B-aligned rows)
    __shared__ float sB[16][64];    // [kk][col]

    const int tid = threadIdx.x;
    const int tr = tid >> 3;        // 0..15 -> rows tr*8..tr*8+7
    const int tc = tid & 7;         // 0..7  -> cols tc*8..tc*8+7

    float acc[8][8];
#pragma unroll
    for (int i = 0; i < 8; ++i)
#pragma unroll
        for (int j = 0; j < 8; ++j) acc[i][j] = 0.f;

    for (int kt = 0; kt < 64; ++kt) {
        const int k0 = kt * 16;
        // A: each thread loads its row's 16 k-values (4x float4), stores transposed
        {
            const float4* srcA = (const float4*)(A + tid * lda + k0);
#pragma unroll
            for (int l = 0; l < 4; ++l) {
                float4 x = srcA[l];
                sA[l*4+0][tid] = x.x;
                sA[l*4+1][tid] = x.y;
                sA[l*4+2][tid] = x.z;
                sA[l*4+3][tid] = x.w;
            }
        }
        // B: 16x64 tile, 2 float4 per thread
        {
#pragma unroll
            for (int l = 0; l < 2; ++l) {
                int i  = tid + l * 128;
                int kk = i >> 4;
                int c4 = (i & 15) << 2;
                *(float4*)&sB[kk][c4] = *(const float4*)(Bm + (k0 + kk) * ldb + c4);
            }
        }
        __syncthreads();
#pragma unroll
        for (int kk = 0; kk < 16; ++kk) {
            float4 a0 = *(float4*)&sA[kk][tr*8];
            float4 a1 = *(float4*)&sA[kk][tr*8+4];
            float4 b0 = *(float4*)&sB[kk][tc*8];
            float4 b1 = *(float4*)&sB[kk][tc*8+4];
            float av[8] = {a0.x,a0.y,a0.z,a0.w,a1.x,a1.y,a1.z,a1.w};
            float bv[8] = {b0.x,b0.y,b0.z,b0.w,b1.x,b1.y,b1.z,b1.w};
#pragma unroll
            for (int i = 0; i < 8; ++i)
#pragma unroll
                for (int j = 0; j < 8; ++j)
                    acc[i][j] = fmaf(av[i], bv[j], acc[i][j]);
        }
        __syncthreads();
    }

#pragma unroll
    for (int i = 0; i < 8; ++i) {
        int r = tr*8 + i;
#pragma unroll
        for (int j = 0; j < 8; j += 4) {
            float4 o;
            o.x = acc[i][j+0] + bias[tc*8+j+0];
            o.y = acc[i][j+1] + bias[tc*8+j+1];
            o.z = acc[i][j+2] + bias[tc*8+j+2];
            o.w = acc[i][j+3] + bias[tc*8+j+3];
            *(float4*)(C + r*ldc + tc*8 + j) = o;
        }
    }
}

// ---------------------------------------------------------------------------
// QKV projections: grid (N/128, H, 3*B), 128 threads
// ---------------------------------------------------------------------------
__global__ __launch_bounds__(128) void proj_kernel(
    const float* __restrict__ Qp, const float* __restrict__ Kp, const float* __restrict__ Vp,
    const float* __restrict__ Wq, const float* __restrict__ bq,
    const float* __restrict__ Wk, const float* __restrict__ bk,
    const float* __restrict__ Wv, const float* __restrict__ bv)
{
    const int op = blockIdx.z >> 2;    // 0:q 1:k 2:v
    const int b  = blockIdx.z & 3;
    const int h  = blockIdx.y;
    const float* X; const float* W; const float* bias; float* dst;
    if (op == 0)      { X = Qp; W = Wq; bias = bq; dst = g_q; }
    else if (op == 1) { X = Kp; W = Wk; bias = bk; dst = g_k; }
    else              { X = Vp; W = Wv; bias = bv; dst = g_v; }

    gemm_128x64(X + (b*N_ + blockIdx.x*128)*DM_, DM_,
                W + h*DM_*DK_, DK_,
                bias + h*DK_,
                dst + ((b*H_ + h)*N_ + blockIdx.x*128)*DK_, DK_);
}

// ---------------------------------------------------------------------------
// Output projection: grid (DM/64, B*N/128), 128 threads
// ---------------------------------------------------------------------------
__global__ __launch_bounds__(128) void outproj_kernel(
    const float* __restrict__ Wo, const float* __restrict__ bo, float* __restrict__ out)
{
    gemm_128x64(g_att + blockIdx.y*128*DM_, DM_,
                Wo + blockIdx.x*64, DM_,
                bo + blockIdx.x*64,
                out + blockIdx.y*128*DM_ + blockIdx.x*64, DM_);
}

// ---------------------------------------------------------------------------
// Flash attention: grid (N/64, H, B), 256 threads, ~70KB dynamic smem.
// Block handles 64 queries; loops over 64-key tiles with online softmax.
// ---------------------------------------------------------------------------
#define FLASH_SMEM (4*64*68*4)

__global__ __launch_bounds__(256) void flash_kernel(const int* __restrict__ mask_ptr)
{
    extern __shared__ float smem[];
    float* sQt = smem;              // [d][r] stride 68 (Q pre-scaled by 1/8)
    float* sKt = smem + 64*68;      // [d][m] stride 68
    float* sV  = smem + 2*64*68;    // [m][v] stride 68
    float* sPt = smem + 3*64*68;    // [m][r] stride 68

    const int tid = threadIdx.x;
    const int qt = blockIdx.x, h = blockIdx.y, b = blockIdx.z;
    const int tr = tid >> 4;        // 0..15 -> rows tr*4..+3
    const int tc = tid & 15;        // 0..15 -> cols tc*4..+3
    const int bh = b*H_ + h;
    const float* qb = g_q + (size_t)bh * N_ * DK_;
    const float* kb = g_k + (size_t)bh * N_ * DK_;
    const float* vb = g_v + (size_t)bh * N_ * DK_;

    const int row = tid >> 2;       // 0..63 (loader mapping)
    const int d0  = (tid & 3) << 4; // 0,16,32,48

    // Load Q tile, transposed + scaled by 1/sqrt(64)
    {
        const float4* src = (const float4*)(qb + (qt*64 + row)*DK_ + d0);
#pragma unroll
        for (int l = 0; l < 4; ++l) {
            float4 x = src[l];
            int dd = d0 + l*4;
            sQt[(dd+0)*68+row] = x.x * 0.125f;
            sQt[(dd+1)*68+row] = x.y * 0.125f;
            sQt[(dd+2)*68+row] = x.z * 0.125f;
            sQt[(dd+3)*68+row] = x.w * 0.125f;
        }
    }

    float m_i[4], l_i[4], o[4][4];
#pragma unroll
    for (int i = 0; i < 4; ++i) {
        m_i[i] = -1e30f; l_i[i] = 0.f;
#pragma unroll
        for (int j = 0; j < 4; ++j) o[i][j] = 0.f;
    }

    const int msk = *mask_ptr;
    const int kt_end = msk ? qt : (N_/64 - 1);

    for (int kt = 0; kt <= kt_end; ++kt) {
        // Load K (transposed) and V (natural) tiles
        {
            const float4* srcK = (const float4*)(kb + (kt*64 + row)*DK_ + d0);
            const float4* srcV = (const float4*)(vb + (kt*64 + row)*DK_ + d0);
#pragma unroll
            for (int l = 0; l < 4; ++l) {
                float4 x = srcK[l];
                int dd = d0 + l*4;
                sKt[(dd+0)*68+row] = x.x;
                sKt[(dd+1)*68+row] = x.y;
                sKt[(dd+2)*68+row] = x.z;
                sKt[(dd+3)*68+row] = x.w;
                float4 y = srcV[l];
                *(float4*)&sV[row*68 + dd] = y;
            }
        }
        __syncthreads();

        // S = Q * K^T (scaled)
        float s[4][4];
#pragma unroll
        for (int i = 0; i < 4; ++i)
#pragma unroll
            for (int j = 0; j < 4; ++j) s[i][j] = 0.f;
#pragma unroll
        for (int kk = 0; kk < 64; ++kk) {
            float4 a  = *(float4*)&sQt[kk*68 + tr*4];
            float4 bb = *(float4*)&sKt[kk*68 + tc*4];
            float av[4] = {a.x, a.y, a.z, a.w};
            float bv[4] = {bb.x, bb.y, bb.z, bb.w};
#pragma unroll
            for (int i = 0; i < 4; ++i)
#pragma unroll
                for (int j = 0; j < 4; ++j)
                    s[i][j] = fmaf(av[i], bv[j], s[i][j]);
        }

        // Causal mask (diagonal tile only)
        if (msk && kt == qt) {
#pragma unroll
            for (int i = 0; i < 4; ++i)
#pragma unroll
                for (int j = 0; j < 4; ++j)
                    if (tc*4 + j > tr*4 + i) s[i][j] = -1e30f;
        }

        // Online softmax: row stats across the 16 lanes (tc) sharing each row
#pragma unroll
        for (int i = 0; i < 4; ++i) {
            float mx = fmaxf(fmaxf(s[i][0], s[i][1]), fmaxf(s[i][2], s[i][3]));
#pragma unroll
            for (int off = 1; off < 16; off <<= 1)
                mx = fmaxf(mx, __shfl_xor_sync(0xffffffffu, mx, off));
            float mnew  = fmaxf(m_i[i], mx);
            float alpha = __expf(m_i[i] - mnew);
            float sum = 0.f;
#pragma unroll
            for (int j = 0; j < 4; ++j) {
                float p = __expf(s[i][j] - mnew);
                sPt[(tc*4 + j)*68 + tr*4 + i] = p;
                sum += p;
            }
#pragma unroll
            for (int off = 1; off < 16; off <<= 1)
                sum += __shfl_xor_sync(0xffffffffu, sum, off);
            l_i[i] = l_i[i] * alpha + sum;
            m_i[i] = mnew;
#pragma unroll
            for (int j = 0; j < 4; ++j) o[i][j] *= alpha;
        }
        __syncthreads();

        // O += P * V
#pragma unroll
        for (int kk = 0; kk < 64; ++kk) {
            float4 a  = *(float4*)&sPt[kk*68 + tr*4];
            float4 bb = *(float4*)&sV[kk*68 + tc*4];
            float av[4] = {a.x, a.y, a.z, a.w};
            float bv[4] = {bb.x, bb.y, bb.z, bb.w};
#pragma unroll
            for (int i = 0; i < 4; ++i)
#pragma unroll
                for (int j = 0; j < 4; ++j)
                    o[i][j] = fmaf(av[i], bv[j], o[i][j]);
        }
        __syncthreads();
    }

    // Normalize + write to concat layout [b, n, h*64 + v]
#pragma unroll
    for (int i = 0; i < 4; ++i) {
        float inv = 1.f / l_i[i];
        int n = qt*64 + tr*4 + i;
        float4 r4;
        r4.x = o[i][0] * inv;
        r4.y = o[i][1] * inv;
        r4.z = o[i][2] * inv;
        r4.w = o[i][3] * inv;
        *(float4*)&g_att[(size_t)(b*N_ + n)*DM_ + h*64 + tc*4] = r4;
    }
}

// ---------------------------------------------------------------------------
extern "C" void kernel_launch(void* const* d_in, const int* in_sizes, int n_in,
                              void* d_out, int out_size)
{
    const float* Q  = (const float*)d_in[0];
    const float* K  = (const float*)d_in[1];
    const float* V  = (const float*)d_in[2];
    const float* Wq = (const float*)d_in[3];
    const float* bq = (const float*)d_in[4];
    const float* Wk = (const float*)d_in[5];
    const float* bk = (const float*)d_in[6];
    const float* Wv = (const float*)d_in[7];
    const float* bv = (const float*)d_in[8];
    const float* Wo = (const float*)d_in[9];
    const float* bo = (const float*)d_in[10];
    const int*  msk = (const int*)d_in[11];
    float* out = (float*)d_out;

    cudaFuncSetAttribute(flash_kernel, cudaFuncAttributeMaxDynamicSharedMemorySize, FLASH_SMEM);

    proj_kernel<<<dim3(N_/128, H_, 3*B_), 128>>>(Q, K, V, Wq, bq, Wk, bk, Wv, bv);
    flash_kernel<<<dim3(N_/64, H_, B_), 256, FLASH_SMEM>>>(msk);
    outproj_kernel<<<dim3(DM_/64, (B_*N_)/128), 128>>>(Wo, bo, out);
}

// round 3
// speedup vs baseline: 2.3314x; 2.3314x over previous
#include <cuda_runtime.h>

#define B_  4
#define N_  2048
#define H_  16
#define DM_ 1024
#define DK_ 64

// Scratch (device globals — no allocation allowed)
__device__ float g_q[B_*H_*N_*DK_];    // [b,h,n,dk]
__device__ float g_k[B_*H_*N_*DK_];
__device__ float g_v[B_*H_*N_*DK_];
__device__ float g_att[B_*N_*DM_];     // [b,n,h*dv]

__device__ __forceinline__ unsigned f2tf(float x) {
    unsigned r;
    asm("cvt.rna.tf32.f32 %0, %1;" : "=r"(r) : "f"(x));
    return r;
}

__device__ __forceinline__ void mma_tf32(float c[4],
    unsigned a0, unsigned a1, unsigned a2, unsigned a3,
    unsigned b0, unsigned b1)
{
    asm("mma.sync.aligned.m16n8k8.row.col.f32.tf32.tf32.f32 "
        "{%0,%1,%2,%3},{%4,%5,%6,%7},{%8,%9},{%0,%1,%2,%3};"
        : "+f"(c[0]), "+f"(c[1]), "+f"(c[2]), "+f"(c[3])
        : "r"(a0), "r"(a1), "r"(a2), "r"(a3), "r"(b0), "r"(b1));
}

// ---------------------------------------------------------------------------
// 128x64 tile tf32 tensor-core GEMM. 256 threads (8 warps), warp tile 32x32,
// BK=32. A row-major [*, lda], B row-major [K, ldb], C row-major.
// ---------------------------------------------------------------------------
__device__ __forceinline__ void gemm128x64_tf32(
    const float* __restrict__ A, int lda,
    const float* __restrict__ Bm, int ldb,
    const float* __restrict__ bias,
    float* __restrict__ C, int ldc, int K)
{
    __shared__ unsigned sA[128][36];   // [row][k], stride 36 (≡4 mod 32)
    __shared__ unsigned sB[32][68];    // [k][n],  stride 68 (≡4 mod 32)

    const int tid  = threadIdx.x;
    const int wid  = tid >> 5;
    const int lane = tid & 31;
    const int g    = lane >> 2;        // groupID 0..7
    const int tig  = lane & 3;         // thread-in-group 0..3
    const int wm   = wid >> 1;         // 0..3 -> rows wm*32
    const int wn   = wid & 1;          // 0..1 -> cols wn*32

    float acc[2][4][4];
#pragma unroll
    for (int mt = 0; mt < 2; ++mt)
#pragma unroll
        for (int nt = 0; nt < 4; ++nt)
#pragma unroll
            for (int i = 0; i < 4; ++i) acc[mt][nt][i] = 0.f;

    for (int k0 = 0; k0 < K; k0 += 32) {
        // Load A tile 128x32 (4 float4 / thread), convert to tf32
#pragma unroll
        for (int t = 0; t < 4; ++t) {
            int idx = tid + t * 256;
            int row = idx >> 3;
            int c4  = (idx & 7) << 2;
            float4 v = *(const float4*)(A + (size_t)row * lda + k0 + c4);
            uint4 u;
            u.x = f2tf(v.x); u.y = f2tf(v.y); u.z = f2tf(v.z); u.w = f2tf(v.w);
            *(uint4*)&sA[row][c4] = u;
        }
        // Load B tile 32x64 (2 float4 / thread)
#pragma unroll
        for (int t = 0; t < 2; ++t) {
            int idx = tid + t * 256;
            int kk  = idx >> 4;
            int c4  = (idx & 15) << 2;
            float4 v = *(const float4*)(Bm + (size_t)(k0 + kk) * ldb + c4);
            uint4 u;
            u.x = f2tf(v.x); u.y = f2tf(v.y); u.z = f2tf(v.z); u.w = f2tf(v.w);
            *(uint4*)&sB[kk][c4] = u;
        }
        __syncthreads();

#pragma unroll
        for (int ks = 0; ks < 4; ++ks) {
            int kb = ks * 8;
            unsigned a[2][4];
#pragma unroll
            for (int mt = 0; mt < 2; ++mt) {
                int r0 = wm * 32 + mt * 16;
                a[mt][0] = sA[r0 + g][kb + tig];
                a[mt][1] = sA[r0 + 8 + g][kb + tig];
                a[mt][2] = sA[r0 + g][kb + tig + 4];
                a[mt][3] = sA[r0 + 8 + g][kb + tig + 4];
            }
#pragma unroll
            for (int nt = 0; nt < 4; ++nt) {
                int n0 = wn * 32 + nt * 8;
                unsigned b0 = sB[kb + tig][n0 + g];
                unsigned b1 = sB[kb + tig + 4][n0 + g];
                mma_tf32(acc[0][nt], a[0][0], a[0][1], a[0][2], a[0][3], b0, b1);
                mma_tf32(acc[1][nt], a[1][0], a[1][1], a[1][2], a[1][3], b0, b1);
            }
        }
        __syncthreads();
    }

    // Epilogue: bias + store (float2, c0/c1 are adjacent columns)
#pragma unroll
    for (int mt = 0; mt < 2; ++mt) {
#pragma unroll
        for (int nt = 0; nt < 4; ++nt) {
            int r = wm * 32 + mt * 16 + g;
            int c = wn * 32 + nt * 8 + tig * 2;
            float2 s0, s1;
            s0.x = acc[mt][nt][0] + bias[c];
            s0.y = acc[mt][nt][1] + bias[c + 1];
            s1.x = acc[mt][nt][2] + bias[c];
            s1.y = acc[mt][nt][3] + bias[c + 1];
            *(float2*)(C + (size_t)r * ldc + c)       = s0;
            *(float2*)(C + (size_t)(r + 8) * ldc + c) = s1;
        }
    }
}

// ---------------------------------------------------------------------------
// QKV projections: grid (N/128, H, 3*B), 256 threads
// ---------------------------------------------------------------------------
__global__ __launch_bounds__(256) void proj_kernel(
    const float* __restrict__ Qp, const float* __restrict__ Kp, const float* __restrict__ Vp,
    const float* __restrict__ Wq, const float* __restrict__ bq,
    const float* __restrict__ Wk, const float* __restrict__ bk,
    const float* __restrict__ Wv, const float* __restrict__ bv)
{
    const int op = blockIdx.z >> 2;    // 0:q 1:k 2:v
    const int b  = blockIdx.z & 3;
    const int h  = blockIdx.y;
    const float* X; const float* W; const float* bias; float* dst;
    if (op == 0)      { X = Qp; W = Wq; bias = bq; dst = g_q; }
    else if (op == 1) { X = Kp; W = Wk; bias = bk; dst = g_k; }
    else              { X = Vp; W = Wv; bias = bv; dst = g_v; }

    gemm128x64_tf32(X + (size_t)(b*N_ + blockIdx.x*128)*DM_, DM_,
                    W + (size_t)h*DM_*DK_, DK_,
                    bias + h*DK_,
                    dst + (size_t)((b*H_ + h)*N_ + blockIdx.x*128)*DK_, DK_, DM_);
}

// ---------------------------------------------------------------------------
// Output projection: grid (DM/64, B*N/128), 256 threads
// ---------------------------------------------------------------------------
__global__ __launch_bounds__(256) void outproj_kernel(
    const float* __restrict__ Wo, const float* __restrict__ bo, float* __restrict__ out)
{
    gemm128x64_tf32(g_att + (size_t)blockIdx.y*128*DM_, DM_,
                    Wo + blockIdx.x*64, DM_,
                    bo + blockIdx.x*64,
                    out + (size_t)blockIdx.y*128*DM_ + blockIdx.x*64, DM_, DM_);
}

// ---------------------------------------------------------------------------
// Flash attention with tf32 mma. grid (N/64, H, B), 128 threads (4 warps).
// Warp w owns query rows w*16..w*16+15 of the 64-row tile.
// ---------------------------------------------------------------------------
#define FLASH_SMEM (4*64*68*4)

__global__ __launch_bounds__(128) void flash_kernel(const int* __restrict__ mask_ptr)
{
    extern __shared__ unsigned fsm[];
    unsigned* sQ = fsm;             // [64][68] tf32, pre-scaled by 1/8
    unsigned* sK = fsm + 64*68;     // [64][68]
    unsigned* sV = fsm + 2*64*68;   // [64][68]
    unsigned* sP = fsm + 3*64*68;   // [64][68]

    const int tid  = threadIdx.x;
    const int wid  = tid >> 5;
    const int lane = tid & 31;
    const int g    = lane >> 2;
    const int tig  = lane & 3;
    const int qt = blockIdx.x, h = blockIdx.y, b = blockIdx.z;
    const int bh = b*H_ + h;
    const float* qb = g_q + (size_t)bh * N_ * DK_;
    const float* kb = g_k + (size_t)bh * N_ * DK_;
    const float* vb = g_v + (size_t)bh * N_ * DK_;

    const int lrow = tid >> 1;            // 0..63
    const int lc0  = (tid & 1) * 32;      // 0 or 32

    // Load Q tile (scaled by 1/sqrt(64)=0.125, tf32)
    {
        const float4* src = (const float4*)(qb + (size_t)(qt*64 + lrow)*DK_ + lc0);
#pragma unroll
        for (int l = 0; l < 8; ++l) {
            float4 v = src[l];
            uint4 u;
            u.x = f2tf(v.x * 0.125f); u.y = f2tf(v.y * 0.125f);
            u.z = f2tf(v.z * 0.125f); u.w = f2tf(v.w * 0.125f);
            *(uint4*)&sQ[lrow*68 + lc0 + l*4] = u;
        }
    }

    float m0 = -1e30f, m1 = -1e30f, l0 = 0.f, l1 = 0.f;
    float o[8][4];
#pragma unroll
    for (int nt = 0; nt < 8; ++nt)
#pragma unroll
        for (int i = 0; i < 4; ++i) o[nt][i] = 0.f;

    const int msk = *mask_ptr;
    const int kt_end = msk ? qt : (N_/64 - 1);
    const int w16 = wid * 16;

    for (int kt = 0; kt <= kt_end; ++kt) {
        // Load K, V tiles (tf32)
        {
            const float4* srcK = (const float4*)(kb + (size_t)(kt*64 + lrow)*DK_ + lc0);
            const float4* srcV = (const float4*)(vb + (size_t)(kt*64 + lrow)*DK_ + lc0);
#pragma unroll
            for (int l = 0; l < 8; ++l) {
                float4 v = srcK[l];
                uint4 u;
                u.x = f2tf(v.x); u.y = f2tf(v.y); u.z = f2tf(v.z); u.w = f2tf(v.w);
                *(uint4*)&sK[lrow*68 + lc0 + l*4] = u;
                float4 w = srcV[l];
                uint4 uv;
                uv.x = f2tf(w.x); uv.y = f2tf(w.y); uv.z = f2tf(w.z); uv.w = f2tf(w.w);
                *(uint4*)&sV[lrow*68 + lc0 + l*4] = uv;
            }
        }
        __syncthreads();

        // S = Q * K^T  (16x64 per warp)
        float s[8][4];
#pragma unroll
        for (int nt = 0; nt < 8; ++nt)
#pragma unroll
            for (int i = 0; i < 4; ++i) s[nt][i] = 0.f;

#pragma unroll
        for (int ks = 0; ks < 8; ++ks) {
            int kbv = ks * 8;
            unsigned a0 = sQ[(w16 + g)*68 + kbv + tig];
            unsigned a1 = sQ[(w16 + 8 + g)*68 + kbv + tig];
            unsigned a2 = sQ[(w16 + g)*68 + kbv + tig + 4];
            unsigned a3 = sQ[(w16 + 8 + g)*68 + kbv + tig + 4];
#pragma unroll
            for (int nt = 0; nt < 8; ++nt) {
                int n0 = nt * 8;
                unsigned b0 = sK[(n0 + g)*68 + kbv + tig];
                unsigned b1 = sK[(n0 + g)*68 + kbv + tig + 4];
                mma_tf32(s[nt], a0, a1, a2, a3, b0, b1);
            }
        }

        // Causal mask on diagonal tile
        if (msk && kt == qt) {
            int ra = w16 + g, rb = w16 + 8 + g;
#pragma unroll
            for (int nt = 0; nt < 8; ++nt) {
                int c0 = nt*8 + tig*2, c1 = c0 + 1;
                if (c0 > ra) s[nt][0] = -1e30f;
                if (c1 > ra) s[nt][1] = -1e30f;
                if (c0 > rb) s[nt][2] = -1e30f;
                if (c1 > rb) s[nt][3] = -1e30f;
            }
        }

        // Online softmax (rows g and g+8; reduce across 4-lane group)
        float mxa = -1e30f, mxb = -1e30f;
#pragma unroll
        for (int nt = 0; nt < 8; ++nt) {
            mxa = fmaxf(mxa, fmaxf(s[nt][0], s[nt][1]));
            mxb = fmaxf(mxb, fmaxf(s[nt][2], s[nt][3]));
        }
#pragma unroll
        for (int off = 1; off < 4; off <<= 1) {
            mxa = fmaxf(mxa, __shfl_xor_sync(0xffffffffu, mxa, off));
            mxb = fmaxf(mxb, __shfl_xor_sync(0xffffffffu, mxb, off));
        }
        float mna = fmaxf(m0, mxa), mnb = fmaxf(m1, mxb);
        float alpa = __expf(m0 - mna), alpb = __expf(m1 - mnb);
        float suma = 0.f, sumb = 0.f;
#pragma unroll
        for (int nt = 0; nt < 8; ++nt) {
            float p0 = __uint_as_float(f2tf(__expf(s[nt][0] - mna)));
            float p1 = __uint_as_float(f2tf(__expf(s[nt][1] - mna)));
            float p2 = __uint_as_float(f2tf(__expf(s[nt][2] - mnb)));
            float p3 = __uint_as_float(f2tf(__expf(s[nt][3] - mnb)));
            suma += p0 + p1; sumb += p2 + p3;
            int c = nt*8 + tig*2;
            float2 pa; pa.x = p0; pa.y = p1;
            float2 pb; pb.x = p2; pb.y = p3;
            *(float2*)&sP[(w16 + g)*68 + c]     = pa;
            *(float2*)&sP[(w16 + 8 + g)*68 + c] = pb;
        }
#pragma unroll
        for (int off = 1; off < 4; off <<= 1) {
            suma += __shfl_xor_sync(0xffffffffu, suma, off);
            sumb += __shfl_xor_sync(0xffffffffu, sumb, off);
        }
        l0 = l0 * alpa + suma; m0 = mna;
        l1 = l1 * alpb + sumb; m1 = mnb;
#pragma unroll
        for (int nt = 0; nt < 8; ++nt) {
            o[nt][0] *= alpa; o[nt][1] *= alpa;
            o[nt][2] *= alpb; o[nt][3] *= alpb;
        }
        __syncwarp();   // warp w's sP rows consumed only by warp w

        // O += P * V  (16x64 per warp)
#pragma unroll
        for (int ks = 0; ks < 8; ++ks) {
            int kbv = ks * 8;
            unsigned a0 = sP[(w16 + g)*68 + kbv + tig];
            unsigned a1 = sP[(w16 + 8 + g)*68 + kbv + tig];
            unsigned a2 = sP[(w16 + g)*68 + kbv + tig + 4];
            unsigned a3 = sP[(w16 + 8 + g)*68 + kbv + tig + 4];
#pragma unroll
            for (int nt = 0; nt < 8; ++nt) {
                int n0 = nt * 8;
                unsigned b0 = sV[(kbv + tig)*68 + n0 + g];
                unsigned b1 = sV[(kbv + tig + 4)*68 + n0 + g];
                mma_tf32(o[nt], a0, a1, a2, a3, b0, b1);
            }
        }
        __syncthreads();   // all warps done with sK/sV before next load
    }

    // Normalize + write to concat layout [b, n, h*64 + col]
    float inva = 1.f / l0, invb = 1.f / l1;
    int ra = qt*64 + w16 + g, rb = ra + 8;
#pragma unroll
    for (int nt = 0; nt < 8; ++nt) {
        int col = h*64 + nt*8 + tig*2;
        float2 va; va.x = o[nt][0]*inva; va.y = o[nt][1]*inva;
        float2 vb2; vb2.x = o[nt][2]*invb; vb2.y = o[nt][3]*invb;
        *(float2*)&g_att[(size_t)(b*N_ + ra)*DM_ + col] = va;
        *(float2*)&g_att[(size_t)(b*N_ + rb)*DM_ + col] = vb2;
    }
}

// ---------------------------------------------------------------------------
extern "C" void kernel_launch(void* const* d_in, const int* in_sizes, int n_in,
                              void* d_out, int out_size)
{
    const float* Q  = (const float*)d_in[0];
    const float* K  = (const float*)d_in[1];
    const float* V  = (const float*)d_in[2];
    const float* Wq = (const float*)d_in[3];
    const float* bq = (const float*)d_in[4];
    const float* Wk = (const float*)d_in[5];
    const float* bk = (const float*)d_in[6];
    const float* Wv = (const float*)d_in[7];
    const float* bv = (const float*)d_in[8];
    const float* Wo = (const float*)d_in[9];
    const float* bo = (const float*)d_in[10];
    const int*  msk = (const int*)d_in[11];
    float* out = (float*)d_out;

    cudaFuncSetAttribute(flash_kernel, cudaFuncAttributeMaxDynamicSharedMemorySize, FLASH_SMEM);

    proj_kernel<<<dim3(N_/128, H_, 3*B_), 256>>>(Q, K, V, Wq, bq, Wk, bk, Wv, bv);
    flash_kernel<<<dim3(N_/64, H_, B_), 128, FLASH_SMEM>>>(msk);
    outproj_kernel<<<dim3(DM_/64, (B_*N_)/128), 256>>>(Wo, bo, out);
}

// round 4
// speedup vs baseline: 3.8058x; 1.6324x over previous
#include <cuda_runtime.h>

#define B_  4
#define N_  2048
#define H_  16
#define DM_ 1024
#define DK_ 64
#define BN_ (B_*N_)          // 8192

// ---------------- scratch (device globals; no allocation allowed) ----------
__device__ unsigned g_x[3][BN_*DM_];     // tf32 inputs (Q,K,V), row-major [bn][d]
__device__ unsigned g_w[3][DM_*DM_];     // tf32 proj weights, layout [k][h*64+j]
__device__ unsigned g_wo[DM_*DM_];       // tf32 Wo, [k][n]
__device__ unsigned g_q[B_*H_*N_*DK_];   // tf32, [b,h,n,dk] (pre-scaled by 0.125)
__device__ unsigned g_k[B_*H_*N_*DK_];
__device__ unsigned g_v[B_*H_*N_*DK_];
__device__ unsigned g_att[BN_*DM_];      // tf32 attention output [bn][h*dv]

__device__ __forceinline__ unsigned f2tf(float x) {
    unsigned r;
    asm("cvt.rna.tf32.f32 %0, %1;" : "=r"(r) : "f"(x));
    return r;
}

__device__ __forceinline__ void mma_tf32(float c[4],
    unsigned a0, unsigned a1, unsigned a2, unsigned a3,
    unsigned b0, unsigned b1)
{
    asm("mma.sync.aligned.m16n8k8.row.col.f32.tf32.tf32.f32 "
        "{%0,%1,%2,%3},{%4,%5,%6,%7},{%8,%9},{%0,%1,%2,%3};"
        : "+f"(c[0]), "+f"(c[1]), "+f"(c[2]), "+f"(c[3])
        : "r"(a0), "r"(a1), "r"(a2), "r"(a3), "r"(b0), "r"(b1));
}

__device__ __forceinline__ void cp16(unsigned d, const void* s) {
    asm volatile("cp.async.cg.shared.global [%0], [%1], 16;" :: "r"(d), "l"(s));
}
__device__ __forceinline__ void cp_commit() { asm volatile("cp.async.commit_group;"); }
__device__ __forceinline__ void cp_wait1()  { asm volatile("cp.async.wait_group 1;"); }
__device__ __forceinline__ void cp_wait0()  { asm volatile("cp.async.wait_group 0;"); }

// ---------------------------------------------------------------------------
// Conversion kernels (fp32 -> tf32 bits)
// ---------------------------------------------------------------------------
__global__ void cvt_in_kernel(const float* __restrict__ Q,
                              const float* __restrict__ K,
                              const float* __restrict__ V)
{
    const float* src = (blockIdx.y == 0) ? Q : (blockIdx.y == 1) ? K : V;
    unsigned* dst = g_x[blockIdx.y];
    int i = blockIdx.x * 256 + threadIdx.x;           // float4 index, < 2097152
    float4 v = ((const float4*)src)[i];
    uint4 u;
    u.x = f2tf(v.x); u.y = f2tf(v.y); u.z = f2tf(v.z); u.w = f2tf(v.w);
    ((uint4*)dst)[i] = u;
}

__global__ void cvt_w_kernel(const float* __restrict__ Wq,
                             const float* __restrict__ Wk,
                             const float* __restrict__ Wv)
{
    const float* w = (blockIdx.y == 0) ? Wq : (blockIdx.y == 1) ? Wk : Wv;
    unsigned* dst = g_w[blockIdx.y];
    int i = blockIdx.x * 256 + threadIdx.x;           // < 1048576
    int k = i >> 10, c = i & 1023;
    int h = c >> 6, j = c & 63;
    dst[i] = f2tf(w[(h << 16) + (k << 6) + j]);       // [h][k][j] -> [k][h*64+j]
}

__global__ void cvt_wo_kernel(const float* __restrict__ Wo)
{
    int i = blockIdx.x * 256 + threadIdx.x;           // float4 index, < 262144
    float4 v = ((const float4*)Wo)[i];
    uint4 u;
    u.x = f2tf(v.x); u.y = f2tf(v.y); u.z = f2tf(v.z); u.w = f2tf(v.w);
    ((uint4*)g_wo)[i] = u;
}

// ---------------------------------------------------------------------------
// 128x128 tf32 GEMM, BK=32, 4 warps (64x64 warp tiles), cp.async 2-stage.
// A row-major [128 rows][1024], B row-major [1024][1024] (col slice applied).
// ---------------------------------------------------------------------------
#define AST 4608                    // 128*36 words per A stage
#define BST 4352                    // 32*136 words per B stage
#define GEMM_SMEM ((AST + BST) * 2 * 4)

struct GemmAcc { float a[4][8][4]; };

__device__ __forceinline__ void gemm_mainloop(
    const unsigned* __restrict__ A,     // block-row base, ld = DM_
    const unsigned* __restrict__ Bw,    // col-slice base, ld = DM_
    unsigned* sA, unsigned* sB, GemmAcc& acc)
{
    const int tid  = threadIdx.x;
    const int wid  = tid >> 5, lane = tid & 31;
    const int g    = lane >> 2, tig = lane & 3;
    const int wm   = wid >> 1, wn = wid & 1;

#pragma unroll
    for (int mt = 0; mt < 4; ++mt)
#pragma unroll
        for (int nt = 0; nt < 8; ++nt)
#pragma unroll
            for (int i = 0; i < 4; ++i) acc.a[mt][nt][i] = 0.f;

    // prologue: stage 0
    {
        unsigned ab = (unsigned)__cvta_generic_to_shared(sA);
        unsigned bb = (unsigned)__cvta_generic_to_shared(sB);
#pragma unroll
        for (int t = 0; t < 8; ++t) {
            int ca = tid + t * 128;
            int row = ca >> 3, cc = ca & 7;
            cp16(ab + (row * 36 + cc * 4) * 4, A + (size_t)row * DM_ + cc * 4);
        }
#pragma unroll
        for (int t = 0; t < 8; ++t) {
            int cb = tid + t * 128;
            int kk = cb >> 5, cc = cb & 31;
            cp16(bb + (kk * 136 + cc * 4) * 4, Bw + (size_t)kk * DM_ + cc * 4);
        }
        cp_commit();
    }

    for (int kt = 0; kt < 32; ++kt) {
        int s = kt & 1;
        if (kt < 31) {
            int k0 = (kt + 1) * 32;
            unsigned ab = (unsigned)__cvta_generic_to_shared(sA + (s ^ 1) * AST);
            unsigned bb = (unsigned)__cvta_generic_to_shared(sB + (s ^ 1) * BST);
#pragma unroll
            for (int t = 0; t < 8; ++t) {
                int ca = tid + t * 128;
                int row = ca >> 3, cc = ca & 7;
                cp16(ab + (row * 36 + cc * 4) * 4, A + (size_t)row * DM_ + k0 + cc * 4);
            }
#pragma unroll
            for (int t = 0; t < 8; ++t) {
                int cb = tid + t * 128;
                int kk = cb >> 5, cc = cb & 31;
                cp16(bb + (kk * 136 + cc * 4) * 4, Bw + (size_t)(k0 + kk) * DM_ + cc * 4);
            }
            cp_commit();
            cp_wait1();
        } else {
            cp_wait0();
        }
        __syncthreads();

        const unsigned* cA = sA + s * AST;
        const unsigned* cB = sB + s * BST;
#pragma unroll
        for (int ks = 0; ks < 4; ++ks) {
            int kb = ks * 8;
            unsigned a[4][4], bf[8][2];
#pragma unroll
            for (int mt = 0; mt < 4; ++mt) {
                int r0 = wm * 64 + mt * 16;
                a[mt][0] = cA[(r0 + g) * 36 + kb + tig];
                a[mt][1] = cA[(r0 + 8 + g) * 36 + kb + tig];
                a[mt][2] = cA[(r0 + g) * 36 + kb + tig + 4];
                a[mt][3] = cA[(r0 + 8 + g) * 36 + kb + tig + 4];
            }
#pragma unroll
            for (int nt = 0; nt < 8; ++nt) {
                int n0 = wn * 64 + nt * 8;
                bf[nt][0] = cB[(kb + tig) * 136 + n0 + g];
                bf[nt][1] = cB[(kb + tig + 4) * 136 + n0 + g];
            }
#pragma unroll
            for (int mt = 0; mt < 4; ++mt)
#pragma unroll
                for (int nt = 0; nt < 8; ++nt)
                    mma_tf32(acc.a[mt][nt], a[mt][0], a[mt][1], a[mt][2], a[mt][3],
                             bf[nt][0], bf[nt][1]);
        }
        __syncthreads();
    }
}

// ---------------------------------------------------------------------------
// Projections: grid (8, 64, 3), 128 threads. C -> g_q/g_k/g_v as tf32.
// ---------------------------------------------------------------------------
__global__ __launch_bounds__(128) void proj_gemm(
    const float* __restrict__ bq, const float* __restrict__ bk,
    const float* __restrict__ bv)
{
    extern __shared__ unsigned sm[];
    unsigned* sA = sm;
    unsigned* sB = sm + 2 * AST;

    const int op = blockIdx.z;
    const unsigned* A  = g_x[op] + (size_t)blockIdx.y * 128 * DM_;
    const unsigned* Bw = g_w[op] + blockIdx.x * 128;
    const float* bias  = (op == 0) ? bq : (op == 1) ? bk : bv;
    unsigned* dst      = (op == 0) ? g_q : (op == 1) ? g_k : g_v;
    const float scale  = (op == 0) ? 0.125f : 1.f;

    GemmAcc acc;
    gemm_mainloop(A, Bw, sA, sB, acc);

    const int tid = threadIdx.x, wid = tid >> 5, lane = tid & 31;
    const int g = lane >> 2, tig = lane & 3;
    const int wm = wid >> 1, wn = wid & 1;

#pragma unroll
    for (int mt = 0; mt < 4; ++mt) {
#pragma unroll
        for (int nt = 0; nt < 8; ++nt) {
#pragma unroll
            for (int half = 0; half < 2; ++half) {
                int r  = wm * 64 + mt * 16 + half * 8 + g;
                int c  = wn * 64 + nt * 8 + tig * 2;
                int rg = blockIdx.y * 128 + r;
                int cg = blockIdx.x * 128 + c;
                int b  = rg >> 11, n = rg & 2047;
                int h  = cg >> 6,  j = cg & 63;
                float v0 = (acc.a[mt][nt][half * 2 + 0] + bias[cg]) * scale;
                float v1 = (acc.a[mt][nt][half * 2 + 1] + bias[cg + 1]) * scale;
                uint2 u; u.x = f2tf(v0); u.y = f2tf(v1);
                *(uint2*)&dst[(size_t)(((b << 4) | h) * N_ + n) * DK_ + j] = u;
            }
        }
    }
}

// ---------------------------------------------------------------------------
// Output projection: grid (8, 64), 128 threads. C -> fp32 out.
// ---------------------------------------------------------------------------
__global__ __launch_bounds__(128) void outproj_gemm(
    const float* __restrict__ bo, float* __restrict__ out)
{
    extern __shared__ unsigned sm[];
    unsigned* sA = sm;
    unsigned* sB = sm + 2 * AST;

    const unsigned* A  = g_att + (size_t)blockIdx.y * 128 * DM_;
    const unsigned* Bw = g_wo + blockIdx.x * 128;

    GemmAcc acc;
    gemm_mainloop(A, Bw, sA, sB, acc);

    const int tid = threadIdx.x, wid = tid >> 5, lane = tid & 31;
    const int g = lane >> 2, tig = lane & 3;
    const int wm = wid >> 1, wn = wid & 1;

#pragma unroll
    for (int mt = 0; mt < 4; ++mt) {
#pragma unroll
        for (int nt = 0; nt < 8; ++nt) {
#pragma unroll
            for (int half = 0; half < 2; ++half) {
                int r  = wm * 64 + mt * 16 + half * 8 + g;
                int c  = wn * 64 + nt * 8 + tig * 2;
                int rg = blockIdx.y * 128 + r;
                int cg = blockIdx.x * 128 + c;
                float2 v;
                v.x = acc.a[mt][nt][half * 2 + 0] + bo[cg];
                v.y = acc.a[mt][nt][half * 2 + 1] + bo[cg + 1];
                *(float2*)(out + (size_t)rg * DM_ + cg) = v;
            }
        }
    }
}

// ---------------------------------------------------------------------------
// Flash attention: grid (16, 16, 4), 128 threads (4 warps x 32 q-rows).
// Q fragments in registers; K/V/P in smem; tf32 mma throughout.
// ---------------------------------------------------------------------------
#define FL_SMEM ((64*68 + 64*72 + 128*68) * 4)    // 70656 B

__global__ __launch_bounds__(128) void flash_kernel(const int* __restrict__ mask_ptr)
{
    extern __shared__ unsigned sm[];
    unsigned* sK = sm;                    // [64][68]
    unsigned* sV = sm + 64 * 68;          // [64][72]
    unsigned* sP = sm + 64 * 68 + 64 * 72;// [128][68]

    const int tid = threadIdx.x, wid = tid >> 5, lane = tid & 31;
    const int g = lane >> 2, tig = lane & 3;
    const int qt = blockIdx.x, h = blockIdx.y, b = blockIdx.z;
    const int bh = b * H_ + h;
    const unsigned* qb = g_q + (size_t)bh * N_ * DK_;
    const unsigned* kb = g_k + (size_t)bh * N_ * DK_;
    const unsigned* vb = g_v + (size_t)bh * N_ * DK_;
    const int w32 = wid * 32;

    // Stage Q tile (128x64) into sP, then pull fragments into registers
#pragma unroll
    for (int t = 0; t < 16; ++t) {
        int idx = tid + t * 128;
        int row = idx >> 4, c4 = (idx & 15) << 2;
        *(uint4*)&sP[row * 68 + c4] =
            *(const uint4*)(qb + (size_t)(qt * 128 + row) * DK_ + c4);
    }
    __syncthreads();

    unsigned q[2][8][4];
#pragma unroll
    for (int mt = 0; mt < 2; ++mt) {
        int r0 = w32 + mt * 16;
#pragma unroll
        for (int ks = 0; ks < 8; ++ks) {
            int kb8 = ks * 8;
            q[mt][ks][0] = sP[(r0 + g) * 68 + kb8 + tig];
            q[mt][ks][1] = sP[(r0 + 8 + g) * 68 + kb8 + tig];
            q[mt][ks][2] = sP[(r0 + g) * 68 + kb8 + tig + 4];
            q[mt][ks][3] = sP[(r0 + 8 + g) * 68 + kb8 + tig + 4];
        }
    }
    // (no sync needed: sP is only overwritten after the first in-loop sync)

    float m[2][2], l[2][2];
    float o[2][8][4];
#pragma unroll
    for (int mt = 0; mt < 2; ++mt) {
        m[mt][0] = m[mt][1] = -1e30f;
        l[mt][0] = l[mt][1] = 0.f;
#pragma unroll
        for (int nt = 0; nt < 8; ++nt)
#pragma unroll
            for (int i = 0; i < 4; ++i) o[mt][nt][i] = 0.f;
    }

    const int msk = *mask_ptr;
    const int kt_end = msk ? (2 * qt + 1) : (N_ / 64 - 1);

    for (int kt = 0; kt <= kt_end; ++kt) {
        // Load K, V tiles (64x64 tf32 each)
#pragma unroll
        for (int t = 0; t < 8; ++t) {
            int idx = tid + t * 128;
            int row = idx >> 4, c4 = (idx & 15) << 2;
            *(uint4*)&sK[row * 68 + c4] =
                *(const uint4*)(kb + (size_t)(kt * 64 + row) * DK_ + c4);
        }
#pragma unroll
        for (int t = 0; t < 8; ++t) {
            int idx = tid + t * 128;
            int row = idx >> 4, c4 = (idx & 15) << 2;
            *(uint4*)&sV[row * 72 + c4] =
                *(const uint4*)(vb + (size_t)(kt * 64 + row) * DK_ + c4);
        }
        __syncthreads();

        // S = Q * K^T  (32x64 per warp)
        float s[2][8][4];
#pragma unroll
        for (int mt = 0; mt < 2; ++mt)
#pragma unroll
            for (int nt = 0; nt < 8; ++nt)
#pragma unroll
                for (int i = 0; i < 4; ++i) s[mt][nt][i] = 0.f;

#pragma unroll
        for (int ks = 0; ks < 8; ++ks) {
            int kb8 = ks * 8;
#pragma unroll
            for (int nt = 0; nt < 8; ++nt) {
                int n0 = nt * 8;
                unsigned b0 = sK[(n0 + g) * 68 + kb8 + tig];
                unsigned b1 = sK[(n0 + g) * 68 + kb8 + tig + 4];
                mma_tf32(s[0][nt], q[0][ks][0], q[0][ks][1], q[0][ks][2], q[0][ks][3], b0, b1);
                mma_tf32(s[1][nt], q[1][ks][0], q[1][ks][1], q[1][ks][2], q[1][ks][3], b0, b1);
            }
        }

        // Causal mask (partial tiles only)
        if (msk && kt >= 2 * qt) {
#pragma unroll
            for (int mt = 0; mt < 2; ++mt) {
                int ra = qt * 128 + w32 + mt * 16 + g;
                int rb = ra + 8;
#pragma unroll
                for (int nt = 0; nt < 8; ++nt) {
                    int c0 = kt * 64 + nt * 8 + tig * 2, c1 = c0 + 1;
                    if (c0 > ra) s[mt][nt][0] = -1e30f;
                    if (c1 > ra) s[mt][nt][1] = -1e30f;
                    if (c0 > rb) s[mt][nt][2] = -1e30f;
                    if (c1 > rb) s[mt][nt][3] = -1e30f;
                }
            }
        }

        // Online softmax + P -> sP (tf32)
#pragma unroll
        for (int mt = 0; mt < 2; ++mt) {
            float mxa = -1e30f, mxb = -1e30f;
#pragma unroll
            for (int nt = 0; nt < 8; ++nt) {
                mxa = fmaxf(mxa, fmaxf(s[mt][nt][0], s[mt][nt][1]));
                mxb = fmaxf(mxb, fmaxf(s[mt][nt][2], s[mt][nt][3]));
            }
#pragma unroll
            for (int off = 1; off < 4; off <<= 1) {
                mxa = fmaxf(mxa, __shfl_xor_sync(0xffffffffu, mxa, off));
                mxb = fmaxf(mxb, __shfl_xor_sync(0xffffffffu, mxb, off));
            }
            float mna = fmaxf(m[mt][0], mxa), mnb = fmaxf(m[mt][1], mxb);
            float ala = __expf(m[mt][0] - mna), alb = __expf(m[mt][1] - mnb);
            float sa = 0.f, sb = 0.f;
            int r0 = w32 + mt * 16;
#pragma unroll
            for (int nt = 0; nt < 8; ++nt) {
                float p0 = __expf(s[mt][nt][0] - mna);
                float p1 = __expf(s[mt][nt][1] - mna);
                float p2 = __expf(s[mt][nt][2] - mnb);
                float p3 = __expf(s[mt][nt][3] - mnb);
                sa += p0 + p1; sb += p2 + p3;
                uint2 ua; ua.x = f2tf(p0); ua.y = f2tf(p1);
                uint2 ub; ub.x = f2tf(p2); ub.y = f2tf(p3);
                *(uint2*)&sP[(r0 + g) * 68 + nt * 8 + tig * 2]     = ua;
                *(uint2*)&sP[(r0 + 8 + g) * 68 + nt * 8 + tig * 2] = ub;
            }
#pragma unroll
            for (int off = 1; off < 4; off <<= 1) {
                sa += __shfl_xor_sync(0xffffffffu, sa, off);
                sb += __shfl_xor_sync(0xffffffffu, sb, off);
            }
            l[mt][0] = l[mt][0] * ala + sa; m[mt][0] = mna;
            l[mt][1] = l[mt][1] * alb + sb; m[mt][1] = mnb;
#pragma unroll
            for (int nt = 0; nt < 8; ++nt) {
                o[mt][nt][0] *= ala; o[mt][nt][1] *= ala;
                o[mt][nt][2] *= alb; o[mt][nt][3] *= alb;
            }
        }
        __syncwarp();   // warp's own sP rows only

        // O += P * V  (32x64 per warp)
#pragma unroll
        for (int ks = 0; ks < 8; ++ks) {
            int kb8 = ks * 8;
            unsigned pa[2][4];
#pragma unroll
            for (int mt = 0; mt < 2; ++mt) {
                int r0 = w32 + mt * 16;
                pa[mt][0] = sP[(r0 + g) * 68 + kb8 + tig];
                pa[mt][1] = sP[(r0 + 8 + g) * 68 + kb8 + tig];
                pa[mt][2] = sP[(r0 + g) * 68 + kb8 + tig + 4];
                pa[mt][3] = sP[(r0 + 8 + g) * 68 + kb8 + tig + 4];
            }
#pragma unroll
            for (int nt = 0; nt < 8; ++nt) {
                int n0 = nt * 8;
                unsigned b0 = sV[(kb8 + tig) * 72 + n0 + g];
                unsigned b1 = sV[(kb8 + tig + 4) * 72 + n0 + g];
                mma_tf32(o[0][nt], pa[0][0], pa[0][1], pa[0][2], pa[0][3], b0, b1);
                mma_tf32(o[1][nt], pa[1][0], pa[1][1], pa[1][2], pa[1][3], b0, b1);
            }
        }
        __syncthreads();   // all warps done with sK/sV before next tile load
    }

    // Normalize + write tf32 to g_att [bn][h*64+col]
#pragma unroll
    for (int mt = 0; mt < 2; ++mt) {
        float ia = 1.f / l[mt][0], ib = 1.f / l[mt][1];
        int na = qt * 128 + w32 + mt * 16 + g;
        int nb = na + 8;
#pragma unroll
        for (int nt = 0; nt < 8; ++nt) {
            int col = h * 64 + nt * 8 + tig * 2;
            uint2 ua, ub;
            ua.x = f2tf(o[mt][nt][0] * ia); ua.y = f2tf(o[mt][nt][1] * ia);
            ub.x = f2tf(o[mt][nt][2] * ib); ub.y = f2tf(o[mt][nt][3] * ib);
            *(uint2*)&g_att[(size_t)(b * N_ + na) * DM_ + col] = ua;
            *(uint2*)&g_att[(size_t)(b * N_ + nb) * DM_ + col] = ub;
        }
    }
}

// ---------------------------------------------------------------------------
extern "C" void kernel_launch(void* const* d_in, const int* in_sizes, int n_in,
                              void* d_out, int out_size)
{
    const float* Q  = (const float*)d_in[0];
    const float* K  = (const float*)d_in[1];
    const float* V  = (const float*)d_in[2];
    const float* Wq = (const float*)d_in[3];
    const float* bq = (const float*)d_in[4];
    const float* Wk = (const float*)d_in[5];
    const float* bk = (const float*)d_in[6];
    const float* Wv = (const float*)d_in[7];
    const float* bv = (const float*)d_in[8];
    const float* Wo = (const float*)d_in[9];
    const float* bo = (const float*)d_in[10];
    const int*  msk = (const int*)d_in[11];
    float* out = (float*)d_out;

    static int attr_done = 0;
    cudaFuncSetAttribute(proj_gemm,    cudaFuncAttributeMaxDynamicSharedMemorySize, GEMM_SMEM);
    cudaFuncSetAttribute(outproj_gemm, cudaFuncAttributeMaxDynamicSharedMemorySize, GEMM_SMEM);
    cudaFuncSetAttribute(flash_kernel, cudaFuncAttributeMaxDynamicSharedMemorySize, FL_SMEM);
    (void)attr_done;

    cvt_in_kernel<<<dim3(8192, 3), 256>>>(Q, K, V);
    cvt_w_kernel<<<dim3(4096, 3), 256>>>(Wq, Wk, Wv);
    cvt_wo_kernel<<<1024, 256>>>(Wo);
    proj_gemm<<<dim3(8, 64, 3), 128, GEMM_SMEM>>>(bq, bk, bv);
    flash_kernel<<<dim3(16, H_, B_), 128, FL_SMEM>>>(msk);
    outproj_gemm<<<dim3(8, 64), 128, GEMM_SMEM>>>(bo, out);
}